// round 1
// baseline (speedup 1.0000x reference)
#include <cuda_runtime.h>
#include <cstdint>
#include <math.h>

// Problem dims
#define B_   256
#define T_   512
#define D_   128
#define H_   1024
#define G_   3072   // 3*H
#define O_   128
#define DIN  257
#define KIN  320    // DIN padded up to multiple of 64

// ---------------- scratch (device globals: allocation-free) ----------------
__device__ float g_gi[(size_t)T_ * B_ * G_];        // [T,B,3H] fp32, 1.61 GB
__device__ float g_xcat[(size_t)(T_ * B_) * KIN];   // packed+padded inputs, 168 MB
__device__ float g_wih[(size_t)G_ * KIN];           // padded W_ih
__device__ float g_h[2][B_ * H_];                   // double-buffered hidden state

// ---------------- helpers ----------------
__device__ __forceinline__ uint32_t f2tf(float x) {
    uint32_t u;
    asm("cvt.rna.tf32.f32 %0, %1;" : "=r"(u) : "f"(x));
    return u;
}
__device__ __forceinline__ uint32_t fbits(float x) { return __float_as_uint(x); }

__device__ __forceinline__ void mma_tf32(float& d0, float& d1, float& d2, float& d3,
                                         uint32_t a0, uint32_t a1, uint32_t a2, uint32_t a3,
                                         uint32_t b0, uint32_t b1) {
    asm volatile(
        "mma.sync.aligned.m16n8k8.row.col.f32.tf32.tf32.f32 "
        "{%0,%1,%2,%3},{%4,%5,%6,%7},{%8,%9},{%0,%1,%2,%3};\n"
        : "+f"(d0), "+f"(d1), "+f"(d2), "+f"(d3)
        : "r"(a0), "r"(a1), "r"(a2), "r"(a3), "r"(b0), "r"(b1));
}

__device__ __forceinline__ float sigmoidf_(float x) { return 1.0f / (1.0f + expf(-x)); }

// ---------------- pack kernels ----------------
// Xcat[row=t*B+b][k] = concat(x[b,t,:], mask[b,t,:], ti[b,t,0], zeros)
__global__ void pack_x(const float* __restrict__ x, const float* __restrict__ mask,
                       const float* __restrict__ ti) {
    size_t idx = (size_t)blockIdx.x * blockDim.x + threadIdx.x;
    const size_t total = (size_t)(T_ * B_) * (KIN / 4);
    if (idx >= total) return;
    int k4 = (int)(idx % (KIN / 4));
    size_t row = idx / (KIN / 4);
    int t = (int)(row >> 8);        // B_=256
    int b = (int)(row & 255);
    float4 v = make_float4(0.f, 0.f, 0.f, 0.f);
    if (k4 < 32) {
        v = *(const float4*)(x + ((size_t)b * T_ + t) * D_ + k4 * 4);
    } else if (k4 < 64) {
        v = *(const float4*)(mask + ((size_t)b * T_ + t) * D_ + (k4 - 32) * 4);
    } else if (k4 == 64) {
        v.x = ti[(size_t)b * T_ + t];
    }
    *(float4*)(g_xcat + row * KIN + k4 * 4) = v;
}

__global__ void pack_w(const float* __restrict__ W_ih) {
    size_t idx = (size_t)blockIdx.x * blockDim.x + threadIdx.x;
    if (idx >= (size_t)G_ * KIN) return;
    int k = (int)(idx % KIN);
    int g = (int)(idx / KIN);
    g_wih[idx] = (k < DIN) ? W_ih[(size_t)g * DIN + k] : 0.0f;
}

__global__ void zero_h0() {
    int idx = blockIdx.x * blockDim.x + threadIdx.x;
    if (idx < B_ * H_) g_h[0][idx] = 0.0f;
}

// ---------------- gi GEMM: g_gi[M=131072, N=3072] = Xcat[M,KIN] * Wih[N,KIN]^T ----------------
// BM=64, BN=64, BK=64, 128 threads (2x2 warps, 32x32 warp tile)
__global__ __launch_bounds__(128) void gi_gemm() {
    __shared__ float sA[64 * 68];
    __shared__ float sB[64 * 68];
    const int tid = threadIdx.x, lane = tid & 31, wid = tid >> 5;
    const int wm = (wid >> 1) * 32, wn = (wid & 1) * 32;
    const int g4 = lane >> 2, tig = lane & 3;
    const size_t m0 = (size_t)blockIdx.x * 64;
    const int n0 = blockIdx.y * 64;

    float acc[2][4][4];
#pragma unroll
    for (int i = 0; i < 2; i++)
#pragma unroll
        for (int j = 0; j < 4; j++)
#pragma unroll
            for (int e = 0; e < 4; e++) acc[i][j][e] = 0.f;

    for (int kc = 0; kc < KIN; kc += 64) {
#pragma unroll
        for (int j = 0; j < 8; j++) {
            int f = tid + 128 * j;
            int r = f >> 4, c4 = f & 15;
            float4 v = *(const float4*)(g_xcat + (m0 + r) * KIN + kc + c4 * 4);
            float4 w;
            w.x = __uint_as_float(f2tf(v.x)); w.y = __uint_as_float(f2tf(v.y));
            w.z = __uint_as_float(f2tf(v.z)); w.w = __uint_as_float(f2tf(v.w));
            *(float4*)(sA + r * 68 + c4 * 4) = w;
        }
#pragma unroll
        for (int j = 0; j < 8; j++) {
            int f = tid + 128 * j;
            int r = f >> 4, c4 = f & 15;
            float4 v = *(const float4*)(g_wih + (size_t)(n0 + r) * KIN + kc + c4 * 4);
            float4 w;
            w.x = __uint_as_float(f2tf(v.x)); w.y = __uint_as_float(f2tf(v.y));
            w.z = __uint_as_float(f2tf(v.z)); w.w = __uint_as_float(f2tf(v.w));
            *(float4*)(sB + r * 68 + c4 * 4) = w;
        }
        __syncthreads();
#pragma unroll
        for (int k8 = 0; k8 < 8; k8++) {
            const int kb = k8 * 8;
            uint32_t a[2][4];
#pragma unroll
            for (int mt = 0; mt < 2; mt++) {
                const float* ap = sA + (wm + mt * 16 + g4) * 68 + kb + tig;
                a[mt][0] = fbits(ap[0]);
                a[mt][1] = fbits(ap[8 * 68]);
                a[mt][2] = fbits(ap[4]);
                a[mt][3] = fbits(ap[8 * 68 + 4]);
            }
#pragma unroll
            for (int nt = 0; nt < 4; nt++) {
                const float* bp = sB + (wn + nt * 8 + g4) * 68 + kb + tig;
                uint32_t b0 = fbits(bp[0]), b1 = fbits(bp[4]);
#pragma unroll
                for (int mt = 0; mt < 2; mt++)
                    mma_tf32(acc[mt][nt][0], acc[mt][nt][1], acc[mt][nt][2], acc[mt][nt][3],
                             a[mt][0], a[mt][1], a[mt][2], a[mt][3], b0, b1);
            }
        }
        __syncthreads();
    }
    // epilogue: write gi
#pragma unroll
    for (int mt = 0; mt < 2; mt++)
#pragma unroll
        for (int nt = 0; nt < 4; nt++)
#pragma unroll
            for (int e = 0; e < 4; e++) {
                size_t row = m0 + wm + mt * 16 + g4 + ((e >> 1) << 3);
                int col = n0 + wn + nt * 8 + 2 * tig + (e & 1);
                g_gi[row * G_ + col] = acc[mt][nt][e];
            }
}

// ---------------- fused GRU step ----------------
// gh = h @ W_hh^T for gates r,z,n on a 64x32 h-tile, then gate math + h update.
// BM=64 (batch), BN=32 (h cols), BK=64, 128 threads (2x2 warps, 32x16 warp tile per gate)
__global__ __launch_bounds__(128) void gru_step(int t,
                                                const float* __restrict__ W_hh,
                                                const float* __restrict__ b_ih,
                                                const float* __restrict__ b_hh) {
    __shared__ float sA[64 * 68];
    __shared__ float sB[96 * 68];
    const float* __restrict__ hin = g_h[t & 1];
    float* __restrict__ hout = g_h[(t + 1) & 1];
    const int tid = threadIdx.x, lane = tid & 31, wid = tid >> 5;
    const int wm = (wid >> 1) * 32, wn = (wid & 1) * 16;
    const int g4 = lane >> 2, tig = lane & 3;
    const int m0 = blockIdx.x * 64, n0 = blockIdx.y * 32;

    float acc[3][2][2][4];
#pragma unroll
    for (int g = 0; g < 3; g++)
#pragma unroll
        for (int i = 0; i < 2; i++)
#pragma unroll
            for (int j = 0; j < 2; j++)
#pragma unroll
                for (int e = 0; e < 4; e++) acc[g][i][j][e] = 0.f;

    for (int kc = 0; kc < H_; kc += 64) {
#pragma unroll
        for (int j = 0; j < 8; j++) {
            int f = tid + 128 * j;
            int r = f >> 4, c4 = f & 15;
            float4 v = *(const float4*)(hin + (size_t)(m0 + r) * H_ + kc + c4 * 4);
            float4 w;
            w.x = __uint_as_float(f2tf(v.x)); w.y = __uint_as_float(f2tf(v.y));
            w.z = __uint_as_float(f2tf(v.z)); w.w = __uint_as_float(f2tf(v.w));
            *(float4*)(sA + r * 68 + c4 * 4) = w;
        }
#pragma unroll
        for (int j = 0; j < 12; j++) {
            int f = tid + 128 * j;
            int r = f >> 4, c4 = f & 15;
            int gate = r >> 5, n = r & 31;
            float4 v = *(const float4*)(W_hh + ((size_t)gate * H_ + n0 + n) * H_ + kc + c4 * 4);
            float4 w;
            w.x = __uint_as_float(f2tf(v.x)); w.y = __uint_as_float(f2tf(v.y));
            w.z = __uint_as_float(f2tf(v.z)); w.w = __uint_as_float(f2tf(v.w));
            *(float4*)(sB + r * 68 + c4 * 4) = w;
        }
        __syncthreads();
#pragma unroll
        for (int k8 = 0; k8 < 8; k8++) {
            const int kb = k8 * 8;
            uint32_t a[2][4];
#pragma unroll
            for (int mt = 0; mt < 2; mt++) {
                const float* ap = sA + (wm + mt * 16 + g4) * 68 + kb + tig;
                a[mt][0] = fbits(ap[0]);
                a[mt][1] = fbits(ap[8 * 68]);
                a[mt][2] = fbits(ap[4]);
                a[mt][3] = fbits(ap[8 * 68 + 4]);
            }
#pragma unroll
            for (int gate = 0; gate < 3; gate++)
#pragma unroll
                for (int nt = 0; nt < 2; nt++) {
                    const float* bp = sB + (gate * 32 + wn + nt * 8 + g4) * 68 + kb + tig;
                    uint32_t b0 = fbits(bp[0]), b1 = fbits(bp[4]);
#pragma unroll
                    for (int mt = 0; mt < 2; mt++)
                        mma_tf32(acc[gate][mt][nt][0], acc[gate][mt][nt][1],
                                 acc[gate][mt][nt][2], acc[gate][mt][nt][3],
                                 a[mt][0], a[mt][1], a[mt][2], a[mt][3], b0, b1);
                }
        }
        __syncthreads();
    }

    // fused gate epilogue
    const float* __restrict__ gi_t = g_gi + (size_t)t * B_ * G_;
#pragma unroll
    for (int mt = 0; mt < 2; mt++)
#pragma unroll
        for (int nt = 0; nt < 2; nt++) {
            const int colbase = n0 + wn + nt * 8 + 2 * tig;
#pragma unroll
            for (int e = 0; e < 4; e++) {
                const int row = m0 + wm + mt * 16 + g4 + ((e >> 1) << 3);
                const int col = colbase + (e & 1);
                const size_t gbase = (size_t)row * G_ + col;
                float ir = gi_t[gbase]            + b_ih[col];
                float iz = gi_t[gbase + H_]       + b_ih[H_ + col];
                float inn = gi_t[gbase + 2 * H_]  + b_ih[2 * H_ + col];
                float r = sigmoidf_(ir + acc[0][mt][nt][e] + b_hh[col]);
                float z = sigmoidf_(iz + acc[1][mt][nt][e] + b_hh[H_ + col]);
                float n = tanhf(inn + r * (acc[2][mt][nt][e] + b_hh[2 * H_ + col]));
                float hp = hin[(size_t)row * H_ + col];
                hout[(size_t)row * H_ + col] = (1.0f - z) * n + z * hp;
            }
        }
}

// ---------------- output head: out[b,o] = h_final[b,:] . W_out[o,:] + b_out[o] ----------------
__global__ void out_gemm(const float* __restrict__ Wout, const float* __restrict__ bout,
                         float* __restrict__ out) {
    const int b = blockIdx.x;
    const int wid = threadIdx.x >> 5, lane = threadIdx.x & 31;
    const int o0 = blockIdx.y * 32 + wid * 4;
    const float* __restrict__ h = g_h[0] + (size_t)b * H_;  // T_=512 even -> final state in buf 0
    float acc[4] = {0.f, 0.f, 0.f, 0.f};
#pragma unroll
    for (int kk = 0; kk < 8; kk++) {
        int k = kk * 128 + lane * 4;
        float4 hv = *(const float4*)(h + k);
#pragma unroll
        for (int j = 0; j < 4; j++) {
            float4 w = *(const float4*)(Wout + (size_t)(o0 + j) * H_ + k);
            acc[j] += hv.x * w.x + hv.y * w.y + hv.z * w.z + hv.w * w.w;
        }
    }
#pragma unroll
    for (int j = 0; j < 4; j++) {
        float v = acc[j];
#pragma unroll
        for (int s = 16; s > 0; s >>= 1) v += __shfl_xor_sync(0xffffffffu, v, s);
        if (lane == 0) out[(size_t)b * O_ + o0 + j] = v + bout[o0 + j];
    }
}

// ---------------- launch ----------------
extern "C" void kernel_launch(void* const* d_in, const int* in_sizes, int n_in,
                              void* d_out, int out_size) {
    const float* x     = (const float*)d_in[0];
    const float* mask  = (const float*)d_in[1];
    const float* ti    = (const float*)d_in[2];
    const float* W_ih  = (const float*)d_in[3];
    const float* W_hh  = (const float*)d_in[4];
    const float* b_ih  = (const float*)d_in[5];
    const float* b_hh  = (const float*)d_in[6];
    const float* W_out = (const float*)d_in[7];
    const float* b_out = (const float*)d_in[8];
    float* out = (float*)d_out;

    {
        size_t total = (size_t)(T_ * B_) * (KIN / 4);
        pack_x<<<(unsigned)((total + 255) / 256), 256>>>(x, mask, ti);
    }
    {
        size_t total = (size_t)G_ * KIN;
        pack_w<<<(unsigned)((total + 255) / 256), 256>>>(W_ih);
    }
    zero_h0<<<(B_ * H_ + 255) / 256, 256>>>();

    gi_gemm<<<dim3((T_ * B_) / 64, G_ / 64), 128>>>();

    for (int t = 0; t < T_; t++)
        gru_step<<<dim3(B_ / 64, H_ / 32), 128>>>(t, W_hh, b_ih, b_hh);

    out_gemm<<<dim3(B_, O_ / 32), 256>>>(W_out, b_out, out);
}